// round 14
// baseline (speedup 1.0000x reference)
#include <cuda_runtime.h>
#include <cuda_bf16.h>
#include <cstdint>

#define N_HALF 4096
#define TWO_N  8192
#define D      8
#define TM     128                    // tile rows
#define NTL    (TWO_N / TM)           // 64 tiles
#define NPAIR  (NTL * (NTL + 1) / 2)  // 2080 tile pairs
#define NSLOT  NTL                    // 64 partial slots per row
#define FINB   256
#define KPAD   72                     // padded K (bf16): 144B rows, conflict-free ldmatrix

#define LN2_F        0.6931471805599453f
#define HALF_LN2SQ_F 0.24022650695910072f
#define HALF_LN2_F   0.34657359027997264f
#define BOUNDARY_F   0.99999f

// __device__ scratch (allocation-free rule)
__device__ float        g_denom[NSLOT * TWO_N];   // 2 MB partials
__device__ float        g_partial[FINB];
__device__ unsigned int g_cnt2;                    // zero-init; reset each run

__device__ __forceinline__ uint32_t smem_u32(const void* p) {
    uint32_t a;
    asm("{ .reg .u64 t; cvta.to.shared.u64 t, %1; cvt.u32.u64 %0, t; }" : "=r"(a) : "l"(p));
    return a;
}
__device__ __forceinline__ float fast_sqrt(float x) { float y; asm("sqrt.approx.f32 %0, %1;" : "=f"(y) : "f"(x)); return y; }
__device__ __forceinline__ float fast_lg2(float x)  { float y; asm("lg2.approx.f32 %0, %1;"  : "=f"(y) : "f"(x)); return y; }
__device__ __forceinline__ float fast_ex2(float x)  { float y; asm("ex2.approx.f32 %0, %1;"  : "=f"(y) : "f"(x)); return y; }
__device__ __forceinline__ float rcp_alu(float d) {
    float y = __int_as_float(0x7EF311C3 - __float_as_int(d));
    y = __fmul_rn(y, fmaf(-d, y, 2.0f));
    y = __fmul_rn(y, fmaf(-d, y, 2.0f));
    return y;
}

__device__ __forceinline__ void ldsm_x4(uint32_t* r, uint32_t addr) {
    asm volatile("ldmatrix.sync.aligned.m8n8.x4.shared.b16 {%0,%1,%2,%3}, [%4];"
        : "=r"(r[0]), "=r"(r[1]), "=r"(r[2]), "=r"(r[3]) : "r"(addr));
}
__device__ __forceinline__ void ldsm_x2(uint32_t& r0, uint32_t& r1, uint32_t addr) {
    asm volatile("ldmatrix.sync.aligned.m8n8.x2.shared.b16 {%0,%1}, [%2];"
        : "=r"(r0), "=r"(r1) : "r"(addr));
}
__device__ __forceinline__ void mma_bf16(float& d0, float& d1, float& d2, float& d3,
                                         const uint32_t* a, uint32_t b0, uint32_t b1) {
    asm volatile(
        "mma.sync.aligned.m16n8k16.row.col.f32.bf16.bf16.f32 "
        "{%0,%1,%2,%3}, {%4,%5,%6,%7}, {%8,%9}, {%0,%1,%2,%3};"
        : "+f"(d0), "+f"(d1), "+f"(d2), "+f"(d3)
        : "r"(a[0]), "r"(a[1]), "r"(a[2]), "r"(a[3]), "r"(b0), "r"(b1));
}

// ---------------- math helpers ----------------------------------------------
__device__ __forceinline__ void load_point(const float* __restrict__ zi,
                                           const float* __restrict__ zj,
                                           int i, float4& a, float4& b) {
    const float* src = (i < N_HALF) ? (zi + (size_t)i * D)
                                    : (zj + (size_t)(i - N_HALF) * D);
    a = *reinterpret_cast<const float4*>(src);
    b = *reinterpret_cast<const float4*>(src + 4);
}
__device__ __forceinline__ float raw8(const float4& a, const float4& b) {
    float d = __fmul_rn(a.x, a.x);
    d = fmaf(a.y, a.y, d); d = fmaf(a.z, a.z, d); d = fmaf(a.w, a.w, d);
    d = fmaf(b.x, b.x, d); d = fmaf(b.y, b.y, d); d = fmaf(b.z, b.z, d);
    d = fmaf(b.w, b.w, d);
    return d;
}
// e = exp(2*sim), sim = 1/(1+arcosh(x)); x already clamped >= 1
__device__ __forceinline__ float chain_e(float x) {
    float x2 = fmaf(x, x, -1.0f);
    float s  = fast_sqrt(x2);
    float l  = fast_lg2(__fadd_rn(x, s));
    float dn = fmaf(l, HALF_LN2SQ_F, HALF_LN2_F);
    return fast_ex2(rcp_alu(dn));
}
__device__ __forceinline__ float chain_sim(float x) {
    float x2 = fmaf(x, x, -1.0f);
    float s  = fast_sqrt(x2);
    float l  = fast_lg2(__fadd_rn(x, s));
    return rcp_alu(fmaf(l, LN2_F, 1.0f));
}

// ---------------------------------------------------------------------------
// Kernel 1: one 128x128 tile pair per block via mma.sync bf16 3-split GEMM,
// transcendental epilogue on fragments, row/col partial denominators.
// grid = 2080, block = 256 (8 warps; warp w owns rows w*16..w*16+15)
// ---------------------------------------------------------------------------
__global__ void __launch_bounds__(256)
pair_mma_kernel(const float* __restrict__ zi, const float* __restrict__ zj) {
    __shared__ __align__(16) __nv_bfloat16 smA[TM * KPAD];   // 18 KB
    __shared__ __align__(16) __nv_bfloat16 smB[TM * KPAD];   // 18 KB
    __shared__ float wcol[8][TM];                            // 4 KB

    const int t    = threadIdx.x;
    const int w    = t >> 5;
    const int lane = t & 31;

    // decode (a, b) from triangle index
    int a = 0, rem = blockIdx.x;
    while (rem >= NTL - a) { rem -= NTL - a; ++a; }
    const int b = a + rem;
    const bool diag = (a == b);

    // ---- stage: threads 0-127 -> A rows (tile a), 128-255 -> B rows (tile b)
    {
        const int r = t & 127;
        const bool sideA = (t < 128);
        const int gi = (sideA ? a : b) * TM + r;
        __nv_bfloat16* base = (sideA ? smA : smB) + r * KPAD;

        float4 za, zb;
        load_point(zi, zj, gi, za, zb);
        float raw = raw8(za, zb);
        float inv = 1.0f / (1.0f - fminf(raw, BOUNDARY_F));

        float v[10];
        if (sideA) {
            float m = __fmul_rn(-4.0f, inv);
            v[0]=__fmul_rn(m,za.x); v[1]=__fmul_rn(m,za.y);
            v[2]=__fmul_rn(m,za.z); v[3]=__fmul_rn(m,za.w);
            v[4]=__fmul_rn(m,zb.x); v[5]=__fmul_rn(m,zb.y);
            v[6]=__fmul_rn(m,zb.z); v[7]=__fmul_rn(m,zb.w);
            float i2 = __fadd_rn(inv, inv);
            v[8]=__fmul_rn(i2,raw); v[9]=i2;
        } else {
            v[0]=__fmul_rn(inv,za.x); v[1]=__fmul_rn(inv,za.y);
            v[2]=__fmul_rn(inv,za.z); v[3]=__fmul_rn(inv,za.w);
            v[4]=__fmul_rn(inv,zb.x); v[5]=__fmul_rn(inv,zb.y);
            v[6]=__fmul_rn(inv,zb.z); v[7]=__fmul_rn(inv,zb.w);
            v[8]=inv; v[9]=__fmul_rn(inv,raw);
        }

        // 3-way bf16 split
        __nv_bfloat16 h[3][10];
        #pragma unroll
        for (int e = 0; e < 10; ++e) {
            h[0][e] = __float2bfloat16(v[e]);
            float r1 = v[e] - __bfloat162float(h[0][e]);
            h[1][e] = __float2bfloat16(r1);
            float r2 = r1 - __bfloat162float(h[1][e]);
            h[2][e] = __float2bfloat16(r2);
        }

        // K segments (products A1B1, A1B2, A2B1, A1B3, A2B2, A3B1)
        const int selA[6] = {0, 0, 1, 0, 1, 2};
        const int selB[6] = {0, 1, 0, 2, 1, 0};
        #pragma unroll
        for (int seg = 0; seg < 6; ++seg) {
            const int sel = sideA ? selA[seg] : selB[seg];
            #pragma unroll
            for (int e = 0; e < 10; ++e)
                base[seg * 10 + e] = h[sel][e];
        }
        #pragma unroll
        for (int c = 60; c < KPAD; ++c)
            base[c] = __float2bfloat16(0.0f);
    }
    __syncthreads();

    // ---- A fragments (per warp, rows w*16..+15), 4 K-steps
    const uint32_t baseA = smem_u32(smA);
    const uint32_t baseB = smem_u32(smB);
    uint32_t afr[4][4];
    {
        uint32_t arow = (uint32_t)(w * 16 + (lane & 15));
        uint32_t addr0 = baseA + arow * (KPAD * 2) + ((uint32_t)(lane >> 4)) * 16;
        #pragma unroll
        for (int k = 0; k < 4; ++k)
            ldsm_x4(afr[k], addr0 + k * 32);
    }
    const uint32_t baddr0 = baseB + (uint32_t)(lane & 7) * (KPAD * 2)
                          + ((uint32_t)((lane >> 3) & 1)) * 16;

    const int rl0 = w * 16 + (lane >> 2);     // local row of d0/d1
    const int cl0 = (lane & 3) * 2;           // local col offset within 8-col tile

    float racc0 = 0.0f, racc1 = 0.0f;

    #pragma unroll 4
    for (int n = 0; n < 16; ++n) {
        float d0 = 0.f, d1 = 0.f, d2 = 0.f, d3 = 0.f;
        #pragma unroll
        for (int k = 0; k < 4; ++k) {
            uint32_t b0, b1;
            ldsm_x2(b0, b1, baddr0 + (uint32_t)(n * 8) * (KPAD * 2) + k * 32);
            mma_bf16(d0, d1, d2, d3, afr[k], b0, b1);
        }
        // epilogue on the 16x8 fragment
        float x0 = fmaxf(__fadd_rn(d0, 1.0f), 1.0f);
        float x1 = fmaxf(__fadd_rn(d1, 1.0f), 1.0f);
        float x2 = fmaxf(__fadd_rn(d2, 1.0f), 1.0f);
        float x3 = fmaxf(__fadd_rn(d3, 1.0f), 1.0f);
        float e0 = chain_e(x0);
        float e1 = chain_e(x1);
        float e2 = chain_e(x2);
        float e3 = chain_e(x3);
        if (diag) {                            // skip self pairs exactly
            int c0 = n * 8 + cl0;
            if (c0 == rl0)          e0 = 0.0f;
            if (c0 + 1 == rl0)      e1 = 0.0f;
            if (c0 == rl0 + 8)      e2 = 0.0f;
            if (c0 + 1 == rl0 + 8)  e3 = 0.0f;
        }
        racc0 += __fadd_rn(e0, e1);
        racc1 += __fadd_rn(e2, e3);
        if (!diag) {
            float cc0 = __fadd_rn(e0, e2);     // col c0 over both row halves
            float cc1 = __fadd_rn(e1, e3);
            #pragma unroll
            for (int m = 4; m <= 16; m <<= 1) {
                cc0 += __shfl_xor_sync(0xFFFFFFFFu, cc0, m);
                cc1 += __shfl_xor_sync(0xFFFFFFFFu, cc1, m);
            }
            if (lane < 4) {                    // full 16-row column sums
                wcol[w][n * 8 + lane * 2]     = cc0;
                wcol[w][n * 8 + lane * 2 + 1] = cc1;
            }
        }
    }

    // row sums: combine the 4 lane%4 groups
    racc0 += __shfl_xor_sync(0xFFFFFFFFu, racc0, 1);
    racc0 += __shfl_xor_sync(0xFFFFFFFFu, racc0, 2);
    racc1 += __shfl_xor_sync(0xFFFFFFFFu, racc1, 1);
    racc1 += __shfl_xor_sync(0xFFFFFFFFu, racc1, 2);
    if ((lane & 3) == 0) {
        const size_t rowb = (size_t)b * TWO_N + a * TM;
        g_denom[rowb + rl0]     = racc0;
        g_denom[rowb + rl0 + 8] = racc1;
    }

    // column sums -> rows of tile b, slot a
    if (!diag) {
        __syncthreads();
        if (t < TM) {
            float c = ((wcol[0][t] + wcol[1][t]) + (wcol[2][t] + wcol[3][t]))
                    + ((wcol[4][t] + wcol[5][t]) + (wcol[6][t] + wcol[7][t]));
            g_denom[(size_t)a * TWO_N + b * TM + t] = c;
        }
    }
}

// ---------------------------------------------------------------------------
// Kernel 2: denom combine (64 slots) + positives + full reduce
// grid = 256, block = 256 (32 rows each); last block finalizes
// ---------------------------------------------------------------------------
__global__ void __launch_bounds__(256)
fin_kernel(const float* __restrict__ zi, const float* __restrict__ zj,
           float* __restrict__ out) {
    __shared__ float sacc[8][32];
    const int t = threadIdx.x;
    const int r = t & 31;
    const int g = t >> 5;          // slot group (8 slots each)
    const int i = blockIdx.x * 32 + r;

    float d = 0.0f;
    #pragma unroll
    for (int c = 0; c < 8; ++c)
        d += g_denom[(size_t)(g * 8 + c) * TWO_N + i];
    sacc[g][r] = d;
    __syncthreads();

    if (g == 0) {
        float denom = 0.0f;
        #pragma unroll
        for (int ww = 0; ww < 8; ++ww) denom += sacc[ww][r];

        // positive pair via scalar fp32 path
        float4 ua, ub, va, vb;
        load_point(zi, zj, i, ua, ub);
        const int pp = (i < N_HALF) ? (i + N_HALF) : (i - N_HALF);
        load_point(zi, zj, pp, va, vb);
        float raw_i = raw8(ua, ub), raw_p = raw8(va, vb);
        float inv_i = 1.0f / (1.0f - fminf(raw_i, BOUNDARY_F));
        float inv_p = 1.0f / (1.0f - fminf(raw_p, BOUNDARY_F));
        float dot = __fmul_rn(ua.x, va.x);
        dot = fmaf(ua.y, va.y, dot); dot = fmaf(ua.z, va.z, dot);
        dot = fmaf(ua.w, va.w, dot); dot = fmaf(ub.x, vb.x, dot);
        dot = fmaf(ub.y, vb.y, dot); dot = fmaf(ub.z, vb.z, dot);
        dot = fmaf(ub.w, vb.w, dot);
        float sqd = fmaxf(raw_i + raw_p - 2.0f * dot, 0.0f);
        float x = fmaxf(fmaf(2.0f * inv_i * inv_p, sqd, 1.0f), 1.0f);
        float sim = chain_sim(x);

        float loss = fast_lg2(denom) * LN2_F - 2.0f * sim;
        #pragma unroll
        for (int s = 16; s > 0; s >>= 1)
            loss += __shfl_xor_sync(0xFFFFFFFFu, loss, s);

        unsigned tk = 0u;
        if (r == 0) {
            g_partial[blockIdx.x] = loss;
            __threadfence();
            tk = atomicAdd(&g_cnt2, 1u) + 1u;
        }
        tk = __shfl_sync(0xFFFFFFFFu, tk, 0);
        if (tk == FINB) {
            __threadfence();
            float v = 0.0f;
            #pragma unroll
            for (int j = 0; j < 8; ++j) v += g_partial[r + j * 32];
            #pragma unroll
            for (int s = 16; s > 0; s >>= 1)
                v += __shfl_xor_sync(0xFFFFFFFFu, v, s);
            if (r == 0) {
                out[0] = v / (float)TWO_N;
                g_cnt2 = 0u;               // reset for next graph replay
            }
        }
    }
}

// ---------------------------------------------------------------------------
extern "C" void kernel_launch(void* const* d_in, const int* in_sizes, int n_in,
                              void* d_out, int out_size) {
    const float* zi = (const float*)d_in[0];
    const float* zj = (const float*)d_in[1];
    float* out = (float*)d_out;

    pair_mma_kernel<<<NPAIR, 256>>>(zi, zj);
    fin_kernel<<<FINB, 256>>>(zi, zj, out);
}

// round 16
// speedup vs baseline: 1.0835x; 1.0835x over previous
#include <cuda_runtime.h>
#include <cuda_bf16.h>
#include <cstdint>

#define N_HALF 4096
#define TWO_N  8192
#define D      8
#define TM     128                    // tile rows
#define NTL    (TWO_N / TM)           // 64 tiles
#define NITEM  (NTL * (NTL + 1) / 2)  // 2080 tile pairs
#define NSLOT  NTL                    // 64 partial slots per row
#define GRID   592                    // 4 blocks/SM x 148 SMs, all resident
#define FINB   256                    // blocks running the fin phase
#define KPAD   40                     // padded K (bf16): 80B rows (16B-aligned, conflict-free)

#define LN2_F        0.6931471805599453f
#define HALF_LN2SQ_F 0.24022650695910072f
#define HALF_LN2_F   0.34657359027997264f
#define BOUNDARY_F   0.99999f

// __device__ scratch (allocation-free rule); counters reset each run.
__device__ float        g_denom[NSLOT * TWO_N];   // 2 MB partials
__device__ float        g_partial[FINB];
__device__ unsigned int g_item;    // work-steal counter
__device__ unsigned int g_cnt;     // phase-1 completion counter
__device__ unsigned int g_cnt2;    // phase-2 completion counter

__device__ __forceinline__ uint32_t smem_u32(const void* p) {
    uint32_t a;
    asm("{ .reg .u64 t; cvta.to.shared.u64 t, %1; cvt.u32.u64 %0, t; }" : "=r"(a) : "l"(p));
    return a;
}
__device__ __forceinline__ float fast_sqrt(float x) { float y; asm("sqrt.approx.f32 %0, %1;" : "=f"(y) : "f"(x)); return y; }
__device__ __forceinline__ float fast_lg2(float x)  { float y; asm("lg2.approx.f32 %0, %1;"  : "=f"(y) : "f"(x)); return y; }
__device__ __forceinline__ float fast_rcp(float x)  { float y; asm("rcp.approx.f32 %0, %1;"  : "=f"(y) : "f"(x)); return y; }
__device__ __forceinline__ float fast_ex2(float x)  { float y; asm("ex2.approx.f32 %0, %1;"  : "=f"(y) : "f"(x)); return y; }

__device__ __forceinline__ void ldsm_x4(uint32_t* r, uint32_t addr) {
    asm volatile("ldmatrix.sync.aligned.m8n8.x4.shared.b16 {%0,%1,%2,%3}, [%4];"
        : "=r"(r[0]), "=r"(r[1]), "=r"(r[2]), "=r"(r[3]) : "r"(addr));
}
__device__ __forceinline__ void ldsm_x2(uint32_t& r0, uint32_t& r1, uint32_t addr) {
    asm volatile("ldmatrix.sync.aligned.m8n8.x2.shared.b16 {%0,%1}, [%2];"
        : "=r"(r0), "=r"(r1) : "r"(addr));
}
__device__ __forceinline__ void mma_bf16(float& d0, float& d1, float& d2, float& d3,
                                         const uint32_t* a, uint32_t b0, uint32_t b1) {
    asm volatile(
        "mma.sync.aligned.m16n8k16.row.col.f32.bf16.bf16.f32 "
        "{%0,%1,%2,%3}, {%4,%5,%6,%7}, {%8,%9}, {%0,%1,%2,%3};"
        : "+f"(d0), "+f"(d1), "+f"(d2), "+f"(d3)
        : "r"(a[0]), "r"(a[1]), "r"(a[2]), "r"(a[3]), "r"(b0), "r"(b1));
}

// ---------------- math helpers ----------------------------------------------
__device__ __forceinline__ void load_point(const float* __restrict__ zi,
                                           const float* __restrict__ zj,
                                           int i, float4& a, float4& b) {
    const float* src = (i < N_HALF) ? (zi + (size_t)i * D)
                                    : (zj + (size_t)(i - N_HALF) * D);
    a = *reinterpret_cast<const float4*>(src);
    b = *reinterpret_cast<const float4*>(src + 4);
}
__device__ __forceinline__ float raw8(const float4& a, const float4& b) {
    float d = __fmul_rn(a.x, a.x);
    d = fmaf(a.y, a.y, d); d = fmaf(a.z, a.z, d); d = fmaf(a.w, a.w, d);
    d = fmaf(b.x, b.x, d); d = fmaf(b.y, b.y, d); d = fmaf(b.z, b.z, d);
    d = fmaf(b.w, b.w, d);
    return d;
}
// e = exp(2*sim), sim = 1/(1+arcosh(x)); x >= 1 on entry.  4 MUFU + 3 FMA.
__device__ __forceinline__ float chain_e(float x) {
    float x2 = fmaf(x, x, -1.0f);
    float s  = fast_sqrt(x2);
    float l  = fast_lg2(__fadd_rn(x, s));
    float dn = fmaf(l, HALF_LN2SQ_F, HALF_LN2_F);
    return fast_ex2(fast_rcp(dn));
}
__device__ __forceinline__ float chain_sim(float x) {
    float x2 = fmaf(x, x, -1.0f);
    float s  = fast_sqrt(x2);
    float l  = fast_lg2(__fadd_rn(x, s));
    return fast_rcp(fmaf(l, LN2_F, 1.0f));
}

// ---------------------------------------------------------------------------
// Fused persistent kernel. Phase 1: work-steal 2080 tile pairs; per pair a
// 128x128 bf16 2-split GEMM (K=32, +1 folded in as a K-column) via mma.sync,
// transcendental epilogue on fragments, row/col partial denominators.
// Global barrier, then phase 2 (fin) on blocks 0..255.
// grid = 592, block = 256 (8 warps; warp w owns rows w*16..w*16+15)
// ---------------------------------------------------------------------------
__global__ void __launch_bounds__(256, 4)
fused_kernel(const float* __restrict__ zi, const float* __restrict__ zj,
             float* __restrict__ out) {
    __shared__ __align__(16) __nv_bfloat16 smA[TM * KPAD];   // 10 KB
    __shared__ __align__(16) __nv_bfloat16 smB[TM * KPAD];   // 10 KB
    __shared__ float wcol[8][TM];                            // 4 KB
    __shared__ unsigned int s_item;

    const int t    = threadIdx.x;
    const int w    = t >> 5;
    const int lane = t & 31;

    const uint32_t baseA = smem_u32(smA);
    const uint32_t baseB = smem_u32(smB);

    // ---------------- Phase 1 ------------------------------------------------
    for (;;) {
        __syncthreads();                       // protect smem reuse + s_item
        if (t == 0) s_item = atomicAdd(&g_item, 1u);
        __syncthreads();
        const int item = (int)s_item;
        if (item >= NITEM) break;              // block-uniform

        // decode (a, b) from triangle index
        int a = 0, rem = item;
        while (rem >= NTL - a) { rem -= NTL - a; ++a; }
        const int b = a + rem;
        const bool diag = (a == b);

        // ---- stage: threads 0-127 -> A rows (tile a), 128-255 -> B (tile b)
        {
            const int r = t & 127;
            const bool sideA = (t < 128);
            const int gi = (sideA ? a : b) * TM + r;
            __nv_bfloat16* base = (sideA ? smA : smB) + r * KPAD;

            float4 za, zb;
            load_point(zi, zj, gi, za, zb);
            float raw = raw8(za, zb);
            float inv = 1.0f / (1.0f - fminf(raw, BOUNDARY_F));

            float v[10];
            if (sideA) {
                float m = __fmul_rn(-4.0f, inv);
                v[0]=__fmul_rn(m,za.x); v[1]=__fmul_rn(m,za.y);
                v[2]=__fmul_rn(m,za.z); v[3]=__fmul_rn(m,za.w);
                v[4]=__fmul_rn(m,zb.x); v[5]=__fmul_rn(m,zb.y);
                v[6]=__fmul_rn(m,zb.z); v[7]=__fmul_rn(m,zb.w);
                float i2 = __fadd_rn(inv, inv);
                v[8]=__fmul_rn(i2,raw); v[9]=i2;
            } else {
                v[0]=__fmul_rn(inv,za.x); v[1]=__fmul_rn(inv,za.y);
                v[2]=__fmul_rn(inv,za.z); v[3]=__fmul_rn(inv,za.w);
                v[4]=__fmul_rn(inv,zb.x); v[5]=__fmul_rn(inv,zb.y);
                v[6]=__fmul_rn(inv,zb.z); v[7]=__fmul_rn(inv,zb.w);
                v[8]=inv; v[9]=__fmul_rn(inv,raw);
            }

            // 2-way bf16 split
            __nv_bfloat16 h[2][10];
            #pragma unroll
            for (int e = 0; e < 10; ++e) {
                h[0][e] = __float2bfloat16(v[e]);
                float r1 = v[e] - __bfloat162float(h[0][e]);
                h[1][e] = __float2bfloat16(r1);
            }

            // K layout: seg0 A1*B1 (0-9), seg1 A1*B2 (10-19), seg2 A2*B1 (20-29),
            // col 30 = 1*1 (folds the +1), col 31.. = 0
            const int selA[3] = {0, 0, 1};
            const int selB[3] = {0, 1, 0};
            #pragma unroll
            for (int seg = 0; seg < 3; ++seg) {
                const int sel = sideA ? selA[seg] : selB[seg];
                #pragma unroll
                for (int e = 0; e < 10; ++e)
                    base[seg * 10 + e] = h[sel][e];
            }
            base[30] = __float2bfloat16(1.0f);
            #pragma unroll
            for (int c = 31; c < KPAD; ++c)
                base[c] = __float2bfloat16(0.0f);
        }
        __syncthreads();

        // ---- A fragments (per warp, rows w*16..+15), 2 K-steps of 16
        uint32_t afr[2][4];
        {
            uint32_t arow = (uint32_t)(w * 16 + (lane & 15));
            uint32_t addr0 = baseA + arow * (KPAD * 2) + ((uint32_t)(lane >> 4)) * 16;
            ldsm_x4(afr[0], addr0);
            ldsm_x4(afr[1], addr0 + 32);
        }
        const uint32_t baddr0 = baseB + (uint32_t)(lane & 7) * (KPAD * 2)
                              + ((uint32_t)((lane >> 3) & 1)) * 16;

        const int rl0 = w * 16 + (lane >> 2);     // local row of d0/d1
        const int cl0 = (lane & 3) * 2;           // col offset within 8-col tile

        float racc0 = 0.0f, racc1 = 0.0f;

        #pragma unroll 4
        for (int n = 0; n < 16; ++n) {
            float d0 = 0.f, d1 = 0.f, d2 = 0.f, d3 = 0.f;
            uint32_t b0, b1;
            ldsm_x2(b0, b1, baddr0 + (uint32_t)(n * 8) * (KPAD * 2));
            mma_bf16(d0, d1, d2, d3, afr[0], b0, b1);
            ldsm_x2(b0, b1, baddr0 + (uint32_t)(n * 8) * (KPAD * 2) + 32);
            mma_bf16(d0, d1, d2, d3, afr[1], b0, b1);

            // epilogue: d already contains the +1 (K-col 30)
            float e0 = chain_e(fmaxf(d0, 1.0f));
            float e1 = chain_e(fmaxf(d1, 1.0f));
            float e2 = chain_e(fmaxf(d2, 1.0f));
            float e3 = chain_e(fmaxf(d3, 1.0f));
            if (diag) {                            // skip self pairs exactly
                int c0 = n * 8 + cl0;
                if (c0 == rl0)          e0 = 0.0f;
                if (c0 + 1 == rl0)      e1 = 0.0f;
                if (c0 == rl0 + 8)      e2 = 0.0f;
                if (c0 + 1 == rl0 + 8)  e3 = 0.0f;
            }
            racc0 += __fadd_rn(e0, e1);
            racc1 += __fadd_rn(e2, e3);
            if (!diag) {
                float cc0 = __fadd_rn(e0, e2);     // col sums over 16 rows
                float cc1 = __fadd_rn(e1, e3);
                #pragma unroll
                for (int m = 4; m <= 16; m <<= 1) {
                    cc0 += __shfl_xor_sync(0xFFFFFFFFu, cc0, m);
                    cc1 += __shfl_xor_sync(0xFFFFFFFFu, cc1, m);
                }
                if (lane < 4) {
                    wcol[w][n * 8 + lane * 2]     = cc0;
                    wcol[w][n * 8 + lane * 2 + 1] = cc1;
                }
            }
        }

        // row sums: combine the 4 lane%4 groups
        racc0 += __shfl_xor_sync(0xFFFFFFFFu, racc0, 1);
        racc0 += __shfl_xor_sync(0xFFFFFFFFu, racc0, 2);
        racc1 += __shfl_xor_sync(0xFFFFFFFFu, racc1, 1);
        racc1 += __shfl_xor_sync(0xFFFFFFFFu, racc1, 2);
        if ((lane & 3) == 0) {
            const size_t rowb = (size_t)b * TWO_N + a * TM;
            g_denom[rowb + rl0]     = racc0;
            g_denom[rowb + rl0 + 8] = racc1;
        }

        // column sums -> rows of tile b, slot a
        if (!diag) {
            __syncthreads();
            if (t < TM) {
                float c = ((wcol[0][t] + wcol[1][t]) + (wcol[2][t] + wcol[3][t]))
                        + ((wcol[4][t] + wcol[5][t]) + (wcol[6][t] + wcol[7][t]));
                g_denom[(size_t)a * TWO_N + b * TM + t] = c;
            }
        }
    }

    // ---------------- Global barrier ----------------------------------------
    __syncthreads();
    __threadfence();
    if (t == 0) atomicAdd(&g_cnt, 1u);

    if (blockIdx.x >= FINB) return;            // non-fin blocks exit

    if (t == 0) {
        while (*((volatile unsigned int*)&g_cnt) < GRID) { __nanosleep(64); }
    }
    __syncthreads();
    __threadfence();                           // acquire: order g_denom reads

    // ---------------- Phase 2: denom combine + loss (32 rows / block) -------
    {
        const int r = t & 31;
        const int g = t >> 5;                  // slot group (8 slots each)
        const int i = blockIdx.x * 32 + r;

        float d = 0.0f;
        #pragma unroll
        for (int c = 0; c < 8; ++c)
            d += g_denom[(size_t)(g * 8 + c) * TWO_N + i];
        wcol[g][r] = d;
        __syncthreads();

        if (g == 0) {
            float denom = ((wcol[0][r] + wcol[1][r]) + (wcol[2][r] + wcol[3][r]))
                        + ((wcol[4][r] + wcol[5][r]) + (wcol[6][r] + wcol[7][r]));

            // positive pair via scalar fp32 path
            float4 ua, ub, va, vb;
            load_point(zi, zj, i, ua, ub);
            const int pp = (i < N_HALF) ? (i + N_HALF) : (i - N_HALF);
            load_point(zi, zj, pp, va, vb);
            float raw_i = raw8(ua, ub), raw_p = raw8(va, vb);
            float inv_i = 1.0f / (1.0f - fminf(raw_i, BOUNDARY_F));
            float inv_p = 1.0f / (1.0f - fminf(raw_p, BOUNDARY_F));
            float dot = __fmul_rn(ua.x, va.x);
            dot = fmaf(ua.y, va.y, dot); dot = fmaf(ua.z, va.z, dot);
            dot = fmaf(ua.w, va.w, dot); dot = fmaf(ub.x, vb.x, dot);
            dot = fmaf(ub.y, vb.y, dot); dot = fmaf(ub.z, vb.z, dot);
            dot = fmaf(ub.w, vb.w, dot);
            float sqd = fmaxf(raw_i + raw_p - 2.0f * dot, 0.0f);
            float x = fmaxf(fmaf(2.0f * inv_i * inv_p, sqd, 1.0f), 1.0f);
            float sim = chain_sim(x);

            float loss = fast_lg2(denom) * LN2_F - 2.0f * sim;
            #pragma unroll
            for (int s = 16; s > 0; s >>= 1)
                loss += __shfl_xor_sync(0xFFFFFFFFu, loss, s);

            unsigned tk = 0u;
            if (r == 0) {
                g_partial[blockIdx.x] = loss;
                __threadfence();
                tk = atomicAdd(&g_cnt2, 1u) + 1u;
            }
            tk = __shfl_sync(0xFFFFFFFFu, tk, 0);
            if (tk == FINB) {                  // last fin block finalizes
                __threadfence();
                float v = 0.0f;
                #pragma unroll
                for (int j = 0; j < 8; ++j) v += g_partial[r + j * 32];
                #pragma unroll
                for (int s = 16; s > 0; s >>= 1)
                    v += __shfl_xor_sync(0xFFFFFFFFu, v, s);
                if (r == 0) {
                    out[0] = v / (float)TWO_N;
                    g_item = 0u;               // reset for next graph replay
                    g_cnt  = 0u;
                    g_cnt2 = 0u;
                    __threadfence();
                }
            }
        }
    }
}

// ---------------------------------------------------------------------------
extern "C" void kernel_launch(void* const* d_in, const int* in_sizes, int n_in,
                              void* d_out, int out_size) {
    const float* zi = (const float*)d_in[0];
    const float* zj = (const float*)d_in[1];
    float* out = (float*)d_out;

    fused_kernel<<<GRID, 256>>>(zi, zj, out);
}